// round 1
// baseline (speedup 1.0000x reference)
#include <cuda_runtime.h>
#include <cstdint>

#define Ecfg 1024
#define Hh   16
#define HKV  4
#define Dd   64

// ---------------- scratch (device globals; no allocation allowed) ----------------
__device__ float g_qraw[2 * 2048 * 1024];
__device__ float g_kraw[2 * 2048 * 256];
__device__ float g_vraw[2 * 2048 * 256];
__device__ float g_qt  [2 * 16 * 2048 * 64];
__device__ float g_kt  [2 * 4  * 2048 * 64];
__device__ float g_vt  [2 * 4  * 2048 * 64];
__device__ float g_attn[2 * 2048 * 1024];

// ---------------- C[M,N] = A[M,K] @ W[N,K]^T  (fp32 tiled) ----------------
// 64x64 block tile, BK=16, 256 threads, 4x4 per thread, float4 smem fragments.
__global__ __launch_bounds__(256) void gemm_nt(
    const float* __restrict__ A, const float* __restrict__ W,
    float* __restrict__ C, int M, int N, int K) {
    __shared__ float As[16][64];
    __shared__ float Ws[16][64];
    const int tid = threadIdx.x;
    const int tx = tid & 15, ty = tid >> 4;
    const int m0 = blockIdx.y * 64, n0 = blockIdx.x * 64;
    const int lm = tid >> 2, lk = (tid & 3) << 2;

    float acc[4][4];
#pragma unroll
    for (int i = 0; i < 4; i++)
#pragma unroll
        for (int j = 0; j < 4; j++) acc[i][j] = 0.f;

    for (int k0 = 0; k0 < K; k0 += 16) {
        float4 av = *reinterpret_cast<const float4*>(&A[(size_t)(m0 + lm) * K + k0 + lk]);
        float4 wv = *reinterpret_cast<const float4*>(&W[(size_t)(n0 + lm) * K + k0 + lk]);
        As[lk + 0][lm] = av.x; As[lk + 1][lm] = av.y; As[lk + 2][lm] = av.z; As[lk + 3][lm] = av.w;
        Ws[lk + 0][lm] = wv.x; Ws[lk + 1][lm] = wv.y; Ws[lk + 2][lm] = wv.z; Ws[lk + 3][lm] = wv.w;
        __syncthreads();
#pragma unroll
        for (int kk = 0; kk < 16; kk++) {
            float4 a = *reinterpret_cast<const float4*>(&As[kk][ty << 2]);
            float4 w = *reinterpret_cast<const float4*>(&Ws[kk][tx << 2]);
            float af[4] = {a.x, a.y, a.z, a.w};
            float wf[4] = {w.x, w.y, w.z, w.w};
#pragma unroll
            for (int i = 0; i < 4; i++)
#pragma unroll
                for (int j = 0; j < 4; j++)
                    acc[i][j] += af[i] * wf[j];
        }
        __syncthreads();
    }
#pragma unroll
    for (int i = 0; i < 4; i++) {
        float4 o = make_float4(acc[i][0], acc[i][1], acc[i][2], acc[i][3]);
        *reinterpret_cast<float4*>(&C[(size_t)(m0 + (ty << 2) + i) * N + n0 + (tx << 2)]) = o;
    }
}

// ---------------- rope + rmsnorm, one warp per (b, t, head) ----------------
// raw layout: [B, T, NH, 64]; dst layout: [B, NH, T, 64]
__global__ void rope_rms_kernel(const float* __restrict__ raw,
                                const float* __restrict__ cosb,
                                const float* __restrict__ sinb,
                                float* __restrict__ dst,
                                int B, int T, int NH) {
    int gw = (blockIdx.x * blockDim.x + threadIdx.x) >> 5;
    int lane = threadIdx.x & 31;
    if (gw >= B * T * NH) return;
    int h = gw % NH;
    int t = (gw / NH) % T;
    int b = gw / (NH * T);
    const float* src = raw + (((size_t)b * T + t) * NH + h) * 64;
    float x1 = src[lane], x2 = src[32 + lane];
    float c = cosb[(size_t)t * 32 + lane];
    float s = sinb[(size_t)t * 32 + lane];
    float r1 = x1 * c + x2 * s;
    float r2 = x2 * c - x1 * s;
    float ss = r1 * r1 + r2 * r2;
#pragma unroll
    for (int o = 16; o; o >>= 1) ss += __shfl_xor_sync(0xffffffffu, ss, o);
    float inv = rsqrtf(ss * (1.f / 64.f) + 1.1920929e-07f);
    float* d = dst + (((size_t)b * NH + h) * T + t) * 64;
    d[lane] = r1 * inv;
    d[32 + lane] = r2 * inv;
}

// ---------------- v = v_raw + 2*sigmoid(x[:32]@Wgate[h]) * ve ----------------
// one warp per (b, t, hkv). dst layout: [B, HKV, T, 64]
__global__ void v_gate_kernel(const float* __restrict__ v_raw,
                              const float* __restrict__ x,
                              const float* __restrict__ ve,
                              const float* __restrict__ Wgate,
                              float* __restrict__ v_t, int B, int T) {
    int gw = (blockIdx.x * blockDim.x + threadIdx.x) >> 5;
    int lane = threadIdx.x & 31;
    if (gw >= B * T * HKV) return;
    int h = gw % HKV;
    int t = (gw / HKV) % T;
    int b = gw / (HKV * T);
    size_t tok = (size_t)b * T + t;
    float g = x[tok * Ecfg + lane] * Wgate[h * 32 + lane];
#pragma unroll
    for (int o = 16; o; o >>= 1) g += __shfl_xor_sync(0xffffffffu, g, o);
    float gate = 2.f / (1.f + __expf(-g));
    const float* vs = v_raw + (tok * HKV + h) * 64;
    const float* ves = ve + (tok * HKV + h) * 64;
    float v1 = vs[lane] + gate * ves[lane];
    float v2 = vs[32 + lane] + gate * ves[32 + lane];
    float* d = v_t + (((size_t)b * HKV + h) * T + t) * 64;
    d[lane] = v1;
    d[32 + lane] = v2;
}

// ---------------- sliding-window flash attention (fp32) ----------------
// 64-query tile per block, 128 threads: thread pair (half 0/1) per query row,
// each half owns 32 key columns of the 64-key tile. Online softmax with
// pair-shuffle combine. q layout [B,H,T,D], k/v [B,HKV,T,D], out [B,T,H,D].
__global__ __launch_bounds__(128) void attn_kernel(
    const float* __restrict__ q, const float* __restrict__ k,
    const float* __restrict__ v, float* __restrict__ out,
    const int* __restrict__ wptr, int T) {
    __shared__ float Qs[64 * 64];
    __shared__ float Ks[64 * 64];
    __shared__ float Vs[64 * 64];
    const int qtile = blockIdx.x, h = blockIdx.y, b = blockIdx.z;
    const int W = wptr[0];
    const int tid = threadIdx.x;
    const int row = tid >> 1, half = tid & 1;
    const int qbase = qtile * 64;
    const int qrow = qbase + row;

    // load + pre-scale Q tile (scale = 1/sqrt(64))
    const float* qptr = q + ((size_t)(b * Hh + h) * T + qbase) * Dd;
#pragma unroll
    for (int i = 0; i < 8; i++) {
        int idx = tid + i * 128;
        float4 t4 = reinterpret_cast<const float4*>(qptr)[idx];
        t4.x *= 0.125f; t4.y *= 0.125f; t4.z *= 0.125f; t4.w *= 0.125f;
        reinterpret_cast<float4*>(Qs)[idx] = t4;
    }
    const int hkv = h >> 2;  // G = 4
    const float* kb = k + (size_t)(b * HKV + hkv) * T * Dd;
    const float* vb = v + (size_t)(b * HKV + hkv) * T * Dd;
    int kmin = qbase - W;
    if (kmin < 0) kmin = 0;
    const int t0 = kmin >> 6;

    float m_run = -1e30f, l_run = 0.f;
    float acc[64];
#pragma unroll
    for (int d = 0; d < 64; d++) acc[d] = 0.f;
    __syncthreads();

    for (int kt = t0; kt <= qtile; kt++) {
        const float4* kp = reinterpret_cast<const float4*>(kb + (size_t)kt * 64 * Dd);
        const float4* vp = reinterpret_cast<const float4*>(vb + (size_t)kt * 64 * Dd);
#pragma unroll
        for (int i = 0; i < 8; i++) {
            int idx = tid + i * 128;
            reinterpret_cast<float4*>(Ks)[idx] = kp[idx];
            reinterpret_cast<float4*>(Vs)[idx] = vp[idx];
        }
        __syncthreads();

        float s[32];
        const int cb = half << 5;
        const float4* qr = reinterpret_cast<const float4*>(Qs + row * 64);
#pragma unroll 4
        for (int c = 0; c < 32; c++) {
            const float4* kr = reinterpret_cast<const float4*>(Ks + (cb + c) * 64);
            float sum = 0.f;
#pragma unroll
            for (int dd = 0; dd < 16; dd++) {
                float4 a = qr[dd];
                float4 bb = kr[dd];
                sum += a.x * bb.x;
                sum += a.y * bb.y;
                sum += a.z * bb.z;
                sum += a.w * bb.w;
            }
            const int col = (kt << 6) + cb + c;
            s[c] = (col <= qrow && col >= qrow - W) ? sum : -1e30f;
        }
        float mloc = -1e30f;
#pragma unroll
        for (int c = 0; c < 32; c++) mloc = fmaxf(mloc, s[c]);
        float mtile = fmaxf(mloc, __shfl_xor_sync(0xffffffffu, mloc, 1));
        float mnew = fmaxf(m_run, mtile);
        float lloc = 0.f;
#pragma unroll
        for (int c = 0; c < 32; c++) {
            float p = (s[c] > -1e29f) ? __expf(s[c] - mnew) : 0.f;
            s[c] = p;
            lloc += p;
        }
        float ltile = lloc + __shfl_xor_sync(0xffffffffu, lloc, 1);
        float f = __expf(m_run - mnew);
        l_run = l_run * f + ltile;
        m_run = mnew;
#pragma unroll
        for (int d = 0; d < 64; d++) acc[d] *= f;
#pragma unroll 2
        for (int c = 0; c < 32; c++) {
            float p = s[c];
            const float4* vr = reinterpret_cast<const float4*>(Vs + (cb + c) * 64);
#pragma unroll
            for (int dd = 0; dd < 16; dd++) {
                float4 vv = vr[dd];
                acc[dd * 4 + 0] += p * vv.x;
                acc[dd * 4 + 1] += p * vv.y;
                acc[dd * 4 + 2] += p * vv.z;
                acc[dd * 4 + 3] += p * vv.w;
            }
        }
        __syncthreads();
    }

    float inv = 1.f / l_run;
    float* op = out + ((size_t)(b * T + qrow) * Hh + h) * Dd;
#pragma unroll
    for (int d = 0; d < 64; d++) {
        float a = acc[d] + __shfl_xor_sync(0xffffffffu, acc[d], 1);
        if (half == 0) op[d] = a * inv;
    }
}

// ---------------- launch ----------------
extern "C" void kernel_launch(void* const* d_in, const int* in_sizes, int n_in,
                              void* d_out, int out_size) {
    const float* x     = (const float*)d_in[0];
    const float* ve    = (const float*)d_in[1];
    const float* cosb  = (const float*)d_in[2];
    const float* sinb  = (const float*)d_in[3];
    const float* Wq    = (const float*)d_in[4];
    const float* Wk    = (const float*)d_in[5];
    const float* Wv    = (const float*)d_in[6];
    const float* Wproj = (const float*)d_in[7];
    const float* Wgate = (const float*)d_in[8];
    const int*   wsz   = (const int*)d_in[9];  // first 4 bytes valid for i32/i64

    int T = in_sizes[2] / 32;          // cos has T * (D/2) elements
    int B = in_sizes[0] / (T * Ecfg);
    int M = B * T;

    float *qraw, *kraw, *vraw, *qt, *kt, *vt, *attn;
    cudaGetSymbolAddress((void**)&qraw, g_qraw);
    cudaGetSymbolAddress((void**)&kraw, g_kraw);
    cudaGetSymbolAddress((void**)&vraw, g_vraw);
    cudaGetSymbolAddress((void**)&qt,   g_qt);
    cudaGetSymbolAddress((void**)&kt,   g_kt);
    cudaGetSymbolAddress((void**)&vt,   g_vt);
    cudaGetSymbolAddress((void**)&attn, g_attn);

    const int KV = HKV * Dd;  // 256

    gemm_nt<<<dim3(Ecfg / 64, M / 64), 256>>>(x, Wq, qraw, M, Ecfg, Ecfg);
    gemm_nt<<<dim3(KV / 64,   M / 64), 256>>>(x, Wk, kraw, M, KV, Ecfg);
    gemm_nt<<<dim3(KV / 64,   M / 64), 256>>>(x, Wv, vraw, M, KV, Ecfg);

    int warpsQ = B * T * Hh;
    int warpsK = B * T * HKV;
    rope_rms_kernel<<<(warpsQ * 32 + 255) / 256, 256>>>(qraw, cosb, sinb, qt, B, T, Hh);
    rope_rms_kernel<<<(warpsK * 32 + 255) / 256, 256>>>(kraw, cosb, sinb, kt, B, T, HKV);
    v_gate_kernel  <<<(warpsK * 32 + 255) / 256, 256>>>(vraw, x, ve, Wgate, vt, B, T);

    attn_kernel<<<dim3(T / 64, Hh, B), 128>>>(qt, kt, vt, attn, wsz, T);

    gemm_nt<<<dim3(Ecfg / 64, M / 64), 256>>>(attn, Wproj, (float*)d_out, M, Ecfg, Ecfg);
}

// round 2
// speedup vs baseline: 1.8450x; 1.8450x over previous
#include <cuda_runtime.h>
#include <mma.h>
#include <cstdint>

using namespace nvcuda;

#define Ecfg 1024
#define Hh   16
#define HKV  4
#define Dd   64

// ---------------- scratch (device globals; no allocation allowed) ----------------
__device__ float g_qraw[2 * 2048 * 1024];
__device__ float g_kraw[2 * 2048 * 256];
__device__ float g_vraw[2 * 2048 * 256];
__device__ float g_qt  [2 * 16 * 2048 * 64];
__device__ float g_kt  [2 * 4  * 2048 * 64];
__device__ float g_vt  [2 * 4  * 2048 * 64];
__device__ float g_attn[2 * 2048 * 1024];

// ================= TF32 wmma GEMM: C[M,N] = A[M,K] @ W[N,K]^T =================
// BM=128, BN=64, BK=32. 256 threads = 8 warps in 4(M) x 2(N); warp tile 32x32.
#define BM 128
#define BN 64
#define BKg 32
#define LDA 40   // smem leading dim (multiple of 8)

__global__ __launch_bounds__(256) void gemm_tf32(
    const float* __restrict__ A, const float* __restrict__ W,
    float* __restrict__ C, int M, int N, int K) {
    __shared__ float As[BM * LDA];
    __shared__ float Ws[BN * LDA];
    const int tid = threadIdx.x;
    const int warp = tid >> 5;
    const int wm = warp >> 1;   // 0..3
    const int wn = warp & 1;    // 0..1
    const int m0 = blockIdx.y * BM, n0 = blockIdx.x * BN;

    wmma::fragment<wmma::accumulator, 16, 16, 8, float> acc[2][2];
#pragma unroll
    for (int i = 0; i < 2; i++)
#pragma unroll
        for (int j = 0; j < 2; j++) wmma::fill_fragment(acc[i][j], 0.f);

    const int lr = tid >> 3;         // 0..31
    const int lc = (tid & 7) << 2;   // 0,4,...,28

    for (int k0 = 0; k0 < K; k0 += BKg) {
#pragma unroll
        for (int p = 0; p < 4; p++) {
            int r = lr + p * 32;
            float4 v = *reinterpret_cast<const float4*>(&A[(size_t)(m0 + r) * K + k0 + lc]);
            float* d = &As[r * LDA + lc];
            d[0] = wmma::__float_to_tf32(v.x); d[1] = wmma::__float_to_tf32(v.y);
            d[2] = wmma::__float_to_tf32(v.z); d[3] = wmma::__float_to_tf32(v.w);
        }
#pragma unroll
        for (int p = 0; p < 2; p++) {
            int r = lr + p * 32;
            float4 v = *reinterpret_cast<const float4*>(&W[(size_t)(n0 + r) * K + k0 + lc]);
            float* d = &Ws[r * LDA + lc];
            d[0] = wmma::__float_to_tf32(v.x); d[1] = wmma::__float_to_tf32(v.y);
            d[2] = wmma::__float_to_tf32(v.z); d[3] = wmma::__float_to_tf32(v.w);
        }
        __syncthreads();
#pragma unroll
        for (int kk = 0; kk < BKg; kk += 8) {
            wmma::fragment<wmma::matrix_a, 16, 16, 8, wmma::precision::tf32, wmma::row_major> a[2];
            wmma::fragment<wmma::matrix_b, 16, 16, 8, wmma::precision::tf32, wmma::col_major> b[2];
#pragma unroll
            for (int i = 0; i < 2; i++)
                wmma::load_matrix_sync(a[i], &As[(wm * 32 + i * 16) * LDA + kk], LDA);
#pragma unroll
            for (int j = 0; j < 2; j++)
                wmma::load_matrix_sync(b[j], &Ws[(wn * 32 + j * 16) * LDA + kk], LDA);
#pragma unroll
            for (int i = 0; i < 2; i++)
#pragma unroll
                for (int j = 0; j < 2; j++)
                    wmma::mma_sync(acc[i][j], a[i], b[j], acc[i][j]);
        }
        __syncthreads();
    }
#pragma unroll
    for (int i = 0; i < 2; i++)
#pragma unroll
        for (int j = 0; j < 2; j++)
            wmma::store_matrix_sync(&C[(size_t)(m0 + wm * 32 + i * 16) * N + n0 + wn * 32 + j * 16],
                                    acc[i][j], N, wmma::mem_row_major);
}

// ---------------- rope + rmsnorm, one warp per (b, t, head) ----------------
__global__ void rope_rms_kernel(const float* __restrict__ raw,
                                const float* __restrict__ cosb,
                                const float* __restrict__ sinb,
                                float* __restrict__ dst,
                                int B, int T, int NH) {
    int gw = (blockIdx.x * blockDim.x + threadIdx.x) >> 5;
    int lane = threadIdx.x & 31;
    if (gw >= B * T * NH) return;
    int h = gw % NH;
    int t = (gw / NH) % T;
    int b = gw / (NH * T);
    const float* src = raw + (((size_t)b * T + t) * NH + h) * 64;
    float x1 = src[lane], x2 = src[32 + lane];
    float c = cosb[(size_t)t * 32 + lane];
    float s = sinb[(size_t)t * 32 + lane];
    float r1 = x1 * c + x2 * s;
    float r2 = x2 * c - x1 * s;
    float ss = r1 * r1 + r2 * r2;
#pragma unroll
    for (int o = 16; o; o >>= 1) ss += __shfl_xor_sync(0xffffffffu, ss, o);
    float inv = rsqrtf(ss * (1.f / 64.f) + 1.1920929e-07f);
    float* d = dst + (((size_t)b * NH + h) * T + t) * 64;
    d[lane] = r1 * inv;
    d[32 + lane] = r2 * inv;
}

// ---------------- v = v_raw + 2*sigmoid(x[:32]@Wgate[h]) * ve ----------------
__global__ void v_gate_kernel(const float* __restrict__ v_raw,
                              const float* __restrict__ x,
                              const float* __restrict__ ve,
                              const float* __restrict__ Wgate,
                              float* __restrict__ v_t, int B, int T) {
    int gw = (blockIdx.x * blockDim.x + threadIdx.x) >> 5;
    int lane = threadIdx.x & 31;
    if (gw >= B * T * HKV) return;
    int h = gw % HKV;
    int t = (gw / HKV) % T;
    int b = gw / (HKV * T);
    size_t tok = (size_t)b * T + t;
    float g = x[tok * Ecfg + lane] * Wgate[h * 32 + lane];
#pragma unroll
    for (int o = 16; o; o >>= 1) g += __shfl_xor_sync(0xffffffffu, g, o);
    float gate = 2.f / (1.f + __expf(-g));
    const float* vs = v_raw + (tok * HKV + h) * 64;
    const float* ves = ve + (tok * HKV + h) * 64;
    float v1 = vs[lane] + gate * ves[lane];
    float v2 = vs[32 + lane] + gate * ves[32 + lane];
    float* d = v_t + (((size_t)b * HKV + h) * T + t) * 64;
    d[lane] = v1;
    d[32 + lane] = v2;
}

// ================ sliding-window flash attention (TF32 tensor cores) ================
// 64-query tile, 128 threads = 4 warps; warp w owns rows [16w, 16w+16).
// Q fragments live in registers for the whole qtile.
#define APAD 72

__global__ __launch_bounds__(128) void attn_tc(
    const float* __restrict__ q, const float* __restrict__ k,
    const float* __restrict__ v, float* __restrict__ out,
    const int* __restrict__ wptr, int T) {
    __shared__ float Ks[64 * APAD];
    __shared__ float Vs[64 * APAD];
    __shared__ float Ss[64 * APAD];
    __shared__ float Os[64 * APAD];

    const int qtile = blockIdx.x, h = blockIdx.y, b = blockIdx.z;
    const int W = wptr[0];
    const int tid = threadIdx.x;
    const int warp = tid >> 5;
    const int row = tid >> 1, half = tid & 1;   // softmax ownership: 2 threads/row
    const int qbase = qtile * 64;
    const int qrow = qbase + row;

    // ---- preload Q fragments from gmem (scaled by 1/8, tf32) ----
    wmma::fragment<wmma::matrix_a, 16, 16, 8, wmma::precision::tf32, wmma::row_major> qf[8];
    {
        const float* qptr = q + ((size_t)(b * Hh + h) * T + qbase + warp * 16) * Dd;
#pragma unroll
        for (int kk = 0; kk < 8; kk++) {
            wmma::load_matrix_sync(qf[kk], qptr + kk * 8, Dd);
#pragma unroll
            for (int e = 0; e < qf[kk].num_elements; e++)
                qf[kk].x[e] = wmma::__float_to_tf32(qf[kk].x[e] * 0.125f);
        }
    }

    // zero O accumulator in smem
    for (int i = tid; i < 64 * APAD; i += 128) Os[i] = 0.f;

    const int hkv = h >> 2;  // G = 4
    const float* kb = k + (size_t)(b * HKV + hkv) * T * Dd;
    const float* vb = v + (size_t)(b * HKV + hkv) * T * Dd;
    int kmin = qbase - W;
    if (kmin < 0) kmin = 0;
    const int t0 = kmin >> 6;

    float m_run = -1e30f, l_run = 0.f;

    for (int kt = t0; kt <= qtile; kt++) {
        __syncthreads();  // previous PV done before overwriting K/V
        // load K,V tiles -> smem (tf32-converted), float4 path
        const float4* kp = reinterpret_cast<const float4*>(kb + (size_t)kt * 64 * Dd);
        const float4* vp = reinterpret_cast<const float4*>(vb + (size_t)kt * 64 * Dd);
#pragma unroll
        for (int i = 0; i < 8; i++) {
            int idx = tid + i * 128;          // 0..1023 float4 slots
            int r = idx >> 4, c4 = (idx & 15) << 2;
            float4 kv = kp[idx];
            float4 vv = vp[idx];
            float4 ko = make_float4(wmma::__float_to_tf32(kv.x), wmma::__float_to_tf32(kv.y),
                                    wmma::__float_to_tf32(kv.z), wmma::__float_to_tf32(kv.w));
            float4 vo = make_float4(wmma::__float_to_tf32(vv.x), wmma::__float_to_tf32(vv.y),
                                    wmma::__float_to_tf32(vv.z), wmma::__float_to_tf32(vv.w));
            *reinterpret_cast<float4*>(&Ks[r * APAD + c4]) = ko;
            *reinterpret_cast<float4*>(&Vs[r * APAD + c4]) = vo;
        }
        __syncthreads();

        // ---- S = Q @ K^T (per warp: 16x64 strip) ----
        {
            wmma::fragment<wmma::accumulator, 16, 16, 8, float> sa[4];
#pragma unroll
            for (int j = 0; j < 4; j++) wmma::fill_fragment(sa[j], 0.f);
#pragma unroll
            for (int kk = 0; kk < 8; kk++) {
#pragma unroll
                for (int j = 0; j < 4; j++) {
                    wmma::fragment<wmma::matrix_b, 16, 16, 8, wmma::precision::tf32, wmma::col_major> bf;
                    wmma::load_matrix_sync(bf, &Ks[(j * 16) * APAD + kk * 8], APAD);
                    wmma::mma_sync(sa[j], qf[kk], bf, sa[j]);
                }
            }
#pragma unroll
            for (int j = 0; j < 4; j++)
                wmma::store_matrix_sync(&Ss[(warp * 16) * APAD + j * 16], sa[j], APAD, wmma::mem_row_major);
        }
        __syncwarp();

        // ---- online softmax on own rows (2 threads per row, 32 cols each) ----
        {
            float* srow = &Ss[row * APAD + half * 32];
            float mloc = -1e30f;
            float sv[32];
#pragma unroll
            for (int c = 0; c < 32; c++) {
                int col = (kt << 6) + (half << 5) + c;
                float s = srow[c];
                s = (col <= qrow && col >= qrow - W) ? s : -1e30f;
                sv[c] = s;
                mloc = fmaxf(mloc, s);
            }
            float mtile = fmaxf(mloc, __shfl_xor_sync(0xffffffffu, mloc, 1));
            float mnew = fmaxf(m_run, mtile);
            float lloc = 0.f;
#pragma unroll
            for (int c = 0; c < 32; c++) {
                float p = (sv[c] > -1e29f) ? __expf(sv[c] - mnew) : 0.f;
                srow[c] = wmma::__float_to_tf32(p);
                lloc += p;
            }
            float ltile = lloc + __shfl_xor_sync(0xffffffffu, lloc, 1);
            float f = __expf(m_run - mnew);
            l_run = l_run * f + ltile;
            m_run = mnew;
            // rescale own O row
            float* orow = &Os[row * APAD + half * 32];
#pragma unroll
            for (int c = 0; c < 32; c++) orow[c] *= f;
        }
        __syncwarp();

        // ---- O += P @ V (per warp: 16x64 strip) ----
        {
            wmma::fragment<wmma::accumulator, 16, 16, 8, float> oa[4];
#pragma unroll
            for (int j = 0; j < 4; j++)
                wmma::load_matrix_sync(oa[j], &Os[(warp * 16) * APAD + j * 16], APAD, wmma::mem_row_major);
#pragma unroll
            for (int kk = 0; kk < 8; kk++) {
                wmma::fragment<wmma::matrix_a, 16, 16, 8, wmma::precision::tf32, wmma::row_major> pf;
                wmma::load_matrix_sync(pf, &Ss[(warp * 16) * APAD + kk * 8], APAD);
#pragma unroll
                for (int j = 0; j < 4; j++) {
                    wmma::fragment<wmma::matrix_b, 16, 16, 8, wmma::precision::tf32, wmma::row_major> bf;
                    wmma::load_matrix_sync(bf, &Vs[(kk * 8) * APAD + j * 16], APAD);
                    wmma::mma_sync(oa[j], pf, bf, oa[j]);
                }
            }
#pragma unroll
            for (int j = 0; j < 4; j++)
                wmma::store_matrix_sync(&Os[(warp * 16) * APAD + j * 16], oa[j], APAD, wmma::mem_row_major);
        }
    }
    __syncwarp();

    // ---- normalize + write out [B,T,H,D] ----
    {
        float inv = 1.f / l_run;
        float* op = out + ((size_t)(b * T + qrow) * Hh + h) * Dd + half * 32;
        const float* orow = &Os[row * APAD + half * 32];
#pragma unroll
        for (int c = 0; c < 32; c += 4) {
            float4 o = make_float4(orow[c] * inv, orow[c + 1] * inv,
                                   orow[c + 2] * inv, orow[c + 3] * inv);
            *reinterpret_cast<float4*>(&op[c]) = o;
        }
    }
}

// ---------------- launch ----------------
extern "C" void kernel_launch(void* const* d_in, const int* in_sizes, int n_in,
                              void* d_out, int out_size) {
    const float* x     = (const float*)d_in[0];
    const float* ve    = (const float*)d_in[1];
    const float* cosb  = (const float*)d_in[2];
    const float* sinb  = (const float*)d_in[3];
    const float* Wq    = (const float*)d_in[4];
    const float* Wk    = (const float*)d_in[5];
    const float* Wv    = (const float*)d_in[6];
    const float* Wproj = (const float*)d_in[7];
    const float* Wgate = (const float*)d_in[8];
    const int*   wsz   = (const int*)d_in[9];

    int T = in_sizes[2] / 32;          // cos has T * (D/2) elements
    int B = in_sizes[0] / (T * Ecfg);
    int M = B * T;

    float *qraw, *kraw, *vraw, *qt, *kt, *vt, *attn;
    cudaGetSymbolAddress((void**)&qraw, g_qraw);
    cudaGetSymbolAddress((void**)&kraw, g_kraw);
    cudaGetSymbolAddress((void**)&vraw, g_vraw);
    cudaGetSymbolAddress((void**)&qt,   g_qt);
    cudaGetSymbolAddress((void**)&kt,   g_kt);
    cudaGetSymbolAddress((void**)&vt,   g_vt);
    cudaGetSymbolAddress((void**)&attn, g_attn);

    const int KV = HKV * Dd;  // 256

    gemm_tf32<<<dim3(Ecfg / BN, M / BM), 256>>>(x, Wq, qraw, M, Ecfg, Ecfg);
    gemm_tf32<<<dim3(KV / BN,   M / BM), 256>>>(x, Wk, kraw, M, KV, Ecfg);
    gemm_tf32<<<dim3(KV / BN,   M / BM), 256>>>(x, Wv, vraw, M, KV, Ecfg);

    int warpsQ = B * T * Hh;
    int warpsK = B * T * HKV;
    rope_rms_kernel<<<(warpsQ * 32 + 255) / 256, 256>>>(qraw, cosb, sinb, qt, B, T, Hh);
    rope_rms_kernel<<<(warpsK * 32 + 255) / 256, 256>>>(kraw, cosb, sinb, kt, B, T, HKV);
    v_gate_kernel  <<<(warpsK * 32 + 255) / 256, 256>>>(vraw, x, ve, Wgate, vt, B, T);

    attn_tc<<<dim3(T / 64, Hh, B), 128>>>(qt, kt, vt, attn, wsz, T);

    gemm_tf32<<<dim3(Ecfg / BN, M / BM), 256>>>(attn, Wproj, (float*)d_out, M, Ecfg, Ecfg);
}

// round 3
// speedup vs baseline: 2.3305x; 1.2632x over previous
#include <cuda_runtime.h>
#include <mma.h>
#include <cstdint>

using namespace nvcuda;

#define Ecfg 1024
#define Hh   16
#define HKV  4
#define Dd   64

// ---------------- scratch (device globals; no allocation allowed) ----------------
__device__ float g_qraw[2 * 2048 * 1024];
__device__ float g_kraw[2 * 2048 * 256];
__device__ float g_vraw[2 * 2048 * 256];
__device__ float g_qt  [2 * 16 * 2048 * 64];
__device__ float g_kt  [2 * 4  * 2048 * 64];
__device__ float g_vt  [2 * 4  * 2048 * 64];
__device__ float g_attn[2 * 2048 * 1024];

// ================= TF32 wmma GEMM: C[M,N] = A[M,K] @ W[N,K]^T =================
// BM=128, BN=64, BK=32, 256 thr = 8 warps (4M x 2N), warp 32x32.
// Double-buffered smem + register prefetch: one __syncthreads per K-slab.
#define BM 128
#define BN 64
#define LDA 40

__device__ __forceinline__ void gemm_tile(
    const float* __restrict__ A, const float* __restrict__ W,
    float* __restrict__ C, int N, int K, int m0, int n0) {
    __shared__ float As[2][BM * LDA];
    __shared__ float Ws[2][BN * LDA];
    const int tid = threadIdx.x;
    const int warp = tid >> 5;
    const int wm = warp >> 1;
    const int wn = warp & 1;
    const int lr = tid >> 3;         // 0..31
    const int lc = (tid & 7) << 2;   // 0,4,...,28

    wmma::fragment<wmma::accumulator, 16, 16, 8, float> acc[2][2];
#pragma unroll
    for (int i = 0; i < 2; i++)
#pragma unroll
        for (int j = 0; j < 2; j++) wmma::fill_fragment(acc[i][j], 0.f);

    float4 ar[4], wr[2];
#pragma unroll
    for (int p = 0; p < 4; p++)
        ar[p] = *reinterpret_cast<const float4*>(&A[(size_t)(m0 + lr + 32 * p) * K + lc]);
#pragma unroll
    for (int p = 0; p < 2; p++)
        wr[p] = *reinterpret_cast<const float4*>(&W[(size_t)(n0 + lr + 32 * p) * K + lc]);

    const int nIter = K >> 5;
    for (int it = 0; it < nIter; ++it) {
        const int buf = it & 1;
        float* as = As[buf];
        float* ws = Ws[buf];
#pragma unroll
        for (int p = 0; p < 4; p++) {
            float* d = &as[(lr + 32 * p) * LDA + lc];
            d[0] = wmma::__float_to_tf32(ar[p].x); d[1] = wmma::__float_to_tf32(ar[p].y);
            d[2] = wmma::__float_to_tf32(ar[p].z); d[3] = wmma::__float_to_tf32(ar[p].w);
        }
#pragma unroll
        for (int p = 0; p < 2; p++) {
            float* d = &ws[(lr + 32 * p) * LDA + lc];
            d[0] = wmma::__float_to_tf32(wr[p].x); d[1] = wmma::__float_to_tf32(wr[p].y);
            d[2] = wmma::__float_to_tf32(wr[p].z); d[3] = wmma::__float_to_tf32(wr[p].w);
        }
        __syncthreads();
        if (it + 1 < nIter) {
            const int k0 = (it + 1) << 5;
#pragma unroll
            for (int p = 0; p < 4; p++)
                ar[p] = *reinterpret_cast<const float4*>(&A[(size_t)(m0 + lr + 32 * p) * K + k0 + lc]);
#pragma unroll
            for (int p = 0; p < 2; p++)
                wr[p] = *reinterpret_cast<const float4*>(&W[(size_t)(n0 + lr + 32 * p) * K + k0 + lc]);
        }
#pragma unroll
        for (int kk = 0; kk < 32; kk += 8) {
            wmma::fragment<wmma::matrix_a, 16, 16, 8, wmma::precision::tf32, wmma::row_major> a[2];
            wmma::fragment<wmma::matrix_b, 16, 16, 8, wmma::precision::tf32, wmma::col_major> b[2];
#pragma unroll
            for (int i = 0; i < 2; i++)
                wmma::load_matrix_sync(a[i], &as[(wm * 32 + i * 16) * LDA + kk], LDA);
#pragma unroll
            for (int j = 0; j < 2; j++)
                wmma::load_matrix_sync(b[j], &ws[(wn * 32 + j * 16) * LDA + kk], LDA);
#pragma unroll
            for (int i = 0; i < 2; i++)
#pragma unroll
                for (int j = 0; j < 2; j++)
                    wmma::mma_sync(acc[i][j], a[i], b[j], acc[i][j]);
        }
        // double buffer: next store targets the other buffer; safety comes from
        // the sync of the following iteration.
    }
#pragma unroll
    for (int i = 0; i < 2; i++)
#pragma unroll
        for (int j = 0; j < 2; j++)
            wmma::store_matrix_sync(&C[(size_t)(m0 + wm * 32 + i * 16) * N + n0 + wn * 32 + j * 16],
                                    acc[i][j], N, wmma::mem_row_major);
}

// generic GEMM (used for output projection)
__global__ __launch_bounds__(256) void gemm_nt(
    const float* __restrict__ A, const float* __restrict__ W,
    float* __restrict__ C, int N, int K) {
    gemm_tile(A, W, C, N, K, blockIdx.y * BM, blockIdx.x * BN);
}

// fused QKV GEMM: 24 n-tiles = 16 (Q) + 4 (K) + 4 (V)
__global__ __launch_bounds__(256) void gemm_qkv(
    const float* __restrict__ x,
    const float* __restrict__ Wq, const float* __restrict__ Wk, const float* __restrict__ Wv,
    float* __restrict__ Cq, float* __restrict__ Ck, float* __restrict__ Cv, int K) {
    const int ng = blockIdx.x * BN;
    const float* W;
    float* C;
    int N, n0;
    if (ng < 1024)      { W = Wq; C = Cq; N = 1024; n0 = ng; }
    else if (ng < 1280) { W = Wk; C = Ck; N = 256;  n0 = ng - 1024; }
    else                { W = Wv; C = Cv; N = 256;  n0 = ng - 1280; }
    gemm_tile(x, W, C, N, K, blockIdx.y * BM, n0);
}

// ---------------- rope + rmsnorm for Q: warp per (b,t,h); grid (T/8, NH, B) ----------------
__global__ void rope_rms_kernel(const float* __restrict__ raw,
                                const float* __restrict__ cosb,
                                const float* __restrict__ sinb,
                                float* __restrict__ dst, int T) {
    const int warp = threadIdx.x >> 5, lane = threadIdx.x & 31;
    const int t = blockIdx.x * 8 + warp;
    const int h = blockIdx.y, b = blockIdx.z;
    const int NH = gridDim.y;
    const float* src = raw + (((size_t)b * T + t) * NH + h) * 64;
    float x1 = src[lane], x2 = src[32 + lane];
    float c = cosb[(size_t)t * 32 + lane];
    float s = sinb[(size_t)t * 32 + lane];
    float r1 = x1 * c + x2 * s;
    float r2 = x2 * c - x1 * s;
    float ss = r1 * r1 + r2 * r2;
#pragma unroll
    for (int o = 16; o; o >>= 1) ss += __shfl_xor_sync(0xffffffffu, ss, o);
    float inv = rsqrtf(ss * (1.f / 64.f) + 1.1920929e-07f);
    float* d = dst + (((size_t)b * NH + h) * T + t) * 64;
    d[lane] = r1 * inv;
    d[32 + lane] = r2 * inv;
}

// ---------------- fused K rope+rms AND V gate: warp per (b,t,hkv); grid (T/8, HKV, B) ----------------
__global__ void kv_post_kernel(const float* __restrict__ kraw,
                               const float* __restrict__ vraw,
                               const float* __restrict__ x,
                               const float* __restrict__ ve,
                               const float* __restrict__ cosb,
                               const float* __restrict__ sinb,
                               const float* __restrict__ Wgate,
                               float* __restrict__ k_t,
                               float* __restrict__ v_t, int T) {
    const int warp = threadIdx.x >> 5, lane = threadIdx.x & 31;
    const int t = blockIdx.x * 8 + warp;
    const int h = blockIdx.y, b = blockIdx.z;
    const size_t tok = (size_t)b * T + t;

    // K: rope + rmsnorm
    {
        const float* src = kraw + (tok * HKV + h) * 64;
        float x1 = src[lane], x2 = src[32 + lane];
        float c = cosb[(size_t)t * 32 + lane];
        float s = sinb[(size_t)t * 32 + lane];
        float r1 = x1 * c + x2 * s;
        float r2 = x2 * c - x1 * s;
        float ss = r1 * r1 + r2 * r2;
#pragma unroll
        for (int o = 16; o; o >>= 1) ss += __shfl_xor_sync(0xffffffffu, ss, o);
        float inv = rsqrtf(ss * (1.f / 64.f) + 1.1920929e-07f);
        float* d = k_t + (((size_t)b * HKV + h) * T + t) * 64;
        d[lane] = r1 * inv;
        d[32 + lane] = r2 * inv;
    }
    // V: v + 2*sigmoid(x[:32] @ Wgate[h]) * ve
    {
        float g = x[tok * Ecfg + lane] * Wgate[h * 32 + lane];
#pragma unroll
        for (int o = 16; o; o >>= 1) g += __shfl_xor_sync(0xffffffffu, g, o);
        float gate = 2.f / (1.f + __expf(-g));
        const float* vs = vraw + (tok * HKV + h) * 64;
        const float* ves = ve + (tok * HKV + h) * 64;
        float* d = v_t + (((size_t)b * HKV + h) * T + t) * 64;
        d[lane] = vs[lane] + gate * ves[lane];
        d[32 + lane] = vs[32 + lane] + gate * ves[32 + lane];
    }
}

// ================ sliding-window flash attention (TF32, fixed-max softmax) ================
// Both q,k are rmsnormed: |q| = |k| = 8, so score = q.k/8 in [-8,8] and the
// diagonal score is exactly 8 -> fixed max M0=8, p=exp(s-8)<=1, row sum l>=1.
// No online rescale => O lives in accumulator fragments across all ktiles.
#define APAD 72

__global__ __launch_bounds__(128) void attn_tc(
    const float* __restrict__ q, const float* __restrict__ k,
    const float* __restrict__ v, float* __restrict__ out,
    const int* __restrict__ wptr, int T) {
    __shared__ float Ks[64 * APAD];
    __shared__ float Vs[64 * APAD];
    __shared__ float Ss[64 * APAD];

    const int qtile = blockIdx.x, h = blockIdx.y, b = blockIdx.z;
    const int W = wptr[0];
    const int tid = threadIdx.x;
    const int warp = tid >> 5;
    const int row = tid >> 1, half = tid & 1;   // 2 threads per query row
    const int qbase = qtile * 64;
    const int qrow = qbase + row;

    // ---- Q fragments (scaled by 1/8, tf32) — persistent ----
    wmma::fragment<wmma::matrix_a, 16, 16, 8, wmma::precision::tf32, wmma::row_major> qf[8];
    {
        const float* qptr = q + ((size_t)(b * Hh + h) * T + qbase + warp * 16) * Dd;
#pragma unroll
        for (int kk = 0; kk < 8; kk++) {
            wmma::load_matrix_sync(qf[kk], qptr + kk * 8, Dd);
#pragma unroll
            for (int e = 0; e < qf[kk].num_elements; e++)
                qf[kk].x[e] = wmma::__float_to_tf32(qf[kk].x[e] * 0.125f);
        }
    }
    // ---- persistent O accumulators (16 rows x 64 cols per warp) ----
    wmma::fragment<wmma::accumulator, 16, 16, 8, float> oa[4];
#pragma unroll
    for (int j = 0; j < 4; j++) wmma::fill_fragment(oa[j], 0.f);

    const int hkv = h >> 2;  // G = 4
    const float* kb = k + (size_t)(b * HKV + hkv) * T * Dd;
    const float* vb = v + (size_t)(b * HKV + hkv) * T * Dd;
    int kmin = qbase - W;
    if (kmin < 0) kmin = 0;
    const int t0 = kmin >> 6;

    float l_run = 0.f;

    for (int kt = t0; kt <= qtile; kt++) {
        __syncthreads();  // all warps done reading previous K/V tiles
        const float4* kp = reinterpret_cast<const float4*>(kb + (size_t)kt * 64 * Dd);
        const float4* vp = reinterpret_cast<const float4*>(vb + (size_t)kt * 64 * Dd);
#pragma unroll
        for (int i = 0; i < 8; i++) {
            int idx = tid + i * 128;
            int r = idx >> 4, c4 = (idx & 15) << 2;
            float4 kv = kp[idx];
            float4 vv = vp[idx];
            float4 ko = make_float4(wmma::__float_to_tf32(kv.x), wmma::__float_to_tf32(kv.y),
                                    wmma::__float_to_tf32(kv.z), wmma::__float_to_tf32(kv.w));
            float4 vo = make_float4(wmma::__float_to_tf32(vv.x), wmma::__float_to_tf32(vv.y),
                                    wmma::__float_to_tf32(vv.z), wmma::__float_to_tf32(vv.w));
            *reinterpret_cast<float4*>(&Ks[r * APAD + c4]) = ko;
            *reinterpret_cast<float4*>(&Vs[r * APAD + c4]) = vo;
        }
        __syncthreads();

        // ---- S = Q @ K^T (warp strip 16x64) ----
        {
            wmma::fragment<wmma::accumulator, 16, 16, 8, float> sa[4];
#pragma unroll
            for (int j = 0; j < 4; j++) wmma::fill_fragment(sa[j], 0.f);
#pragma unroll
            for (int kk = 0; kk < 8; kk++) {
#pragma unroll
                for (int j = 0; j < 4; j++) {
                    wmma::fragment<wmma::matrix_b, 16, 16, 8, wmma::precision::tf32, wmma::col_major> bf;
                    wmma::load_matrix_sync(bf, &Ks[(j * 16) * APAD + kk * 8], APAD);
                    wmma::mma_sync(sa[j], qf[kk], bf, sa[j]);
                }
            }
#pragma unroll
            for (int j = 0; j < 4; j++)
                wmma::store_matrix_sync(&Ss[(warp * 16) * APAD + j * 16], sa[j], APAD, wmma::mem_row_major);
        }
        __syncwarp();

        // ---- fixed-max softmax on own rows (mask, p = exp(s-8)) ----
        {
            float* srow = &Ss[row * APAD + half * 32];
            float lloc = 0.f;
#pragma unroll
            for (int c = 0; c < 32; c++) {
                int col = (kt << 6) + (half << 5) + c;
                float p = 0.f;
                if (col <= qrow && col >= qrow - W) {
                    p = __expf(srow[c] - 8.f);
                    lloc += p;
                }
                srow[c] = wmma::__float_to_tf32(p);
            }
            l_run += lloc;
        }
        __syncwarp();

        // ---- O += P @ V (into persistent fragments) ----
#pragma unroll
        for (int kk = 0; kk < 8; kk++) {
            wmma::fragment<wmma::matrix_a, 16, 16, 8, wmma::precision::tf32, wmma::row_major> pf;
            wmma::load_matrix_sync(pf, &Ss[(warp * 16) * APAD + kk * 8], APAD);
#pragma unroll
            for (int j = 0; j < 4; j++) {
                wmma::fragment<wmma::matrix_b, 16, 16, 8, wmma::precision::tf32, wmma::row_major> bf;
                wmma::load_matrix_sync(bf, &Vs[(kk * 8) * APAD + j * 16], APAD);
                wmma::mma_sync(oa[j], pf, bf, oa[j]);
            }
        }
    }

    // ---- stage O to smem (own strip), normalize, write [B,T,H,D] ----
#pragma unroll
    for (int j = 0; j < 4; j++)
        wmma::store_matrix_sync(&Ss[(warp * 16) * APAD + j * 16], oa[j], APAD, wmma::mem_row_major);
    __syncwarp();
    {
        float l_tot = l_run + __shfl_xor_sync(0xffffffffu, l_run, 1);
        float inv = 1.f / l_tot;
        float* op = out + ((size_t)(b * T + qrow) * Hh + h) * Dd + half * 32;
        const float* orow = &Ss[row * APAD + half * 32];
#pragma unroll
        for (int c = 0; c < 32; c += 4) {
            float4 o = make_float4(orow[c] * inv, orow[c + 1] * inv,
                                   orow[c + 2] * inv, orow[c + 3] * inv);
            *reinterpret_cast<float4*>(&op[c]) = o;
        }
    }
}

// ---------------- launch ----------------
extern "C" void kernel_launch(void* const* d_in, const int* in_sizes, int n_in,
                              void* d_out, int out_size) {
    const float* x     = (const float*)d_in[0];
    const float* ve    = (const float*)d_in[1];
    const float* cosb  = (const float*)d_in[2];
    const float* sinb  = (const float*)d_in[3];
    const float* Wq    = (const float*)d_in[4];
    const float* Wk    = (const float*)d_in[5];
    const float* Wv    = (const float*)d_in[6];
    const float* Wproj = (const float*)d_in[7];
    const float* Wgate = (const float*)d_in[8];
    const int*   wsz   = (const int*)d_in[9];

    int T = in_sizes[2] / 32;
    int B = in_sizes[0] / (T * Ecfg);
    int M = B * T;

    float *qraw, *kraw, *vraw, *qt, *kt, *vt, *attn;
    cudaGetSymbolAddress((void**)&qraw, g_qraw);
    cudaGetSymbolAddress((void**)&kraw, g_kraw);
    cudaGetSymbolAddress((void**)&vraw, g_vraw);
    cudaGetSymbolAddress((void**)&qt,   g_qt);
    cudaGetSymbolAddress((void**)&kt,   g_kt);
    cudaGetSymbolAddress((void**)&vt,   g_vt);
    cudaGetSymbolAddress((void**)&attn, g_attn);

    gemm_qkv<<<dim3(1536 / BN, M / BM), 256>>>(x, Wq, Wk, Wv, qraw, kraw, vraw, Ecfg);

    rope_rms_kernel<<<dim3(T / 8, Hh, B), 256>>>(qraw, cosb, sinb, qt, T);
    kv_post_kernel <<<dim3(T / 8, HKV, B), 256>>>(kraw, vraw, x, ve, cosb, sinb, Wgate, kt, vt, T);

    attn_tc<<<dim3(T / 64, Hh, B), 128>>>(qt, kt, vt, attn, wsz, T);

    gemm_nt<<<dim3(Ecfg / BN, M / BM), 256>>>(attn, Wproj, (float*)d_out, Ecfg, Ecfg);
}